// round 17
// baseline (speedup 1.0000x reference)
#include <cuda_runtime.h>
#include <cuda_bf16.h>
#include <mma.h>
#include <math.h>
#include <stdint.h>

using namespace nvcuda;

#define BB 256
#define TT 256
#define FF 64
#define UU 512
#define GG 2048

#define NTILES 32
#define NCOL   64
#define KC     64
#define STAGES 3
#define NTHR   256
#define NCTA   128u
#define C1N    9       // layer1 chunks (x:1 + h1:8)
#define CTOT   25      // + layer2 chunks (h1:8 + h2:8)

#define LDA 72
#define LDB 72
#define LDZ 72
#define A_STG   (64 * LDA * 2)               // 9216
#define B_STG   (KC * LDB * 2)               // 9216
#define A_OFF   0
#define B1_OFF  (STAGES * A_STG)             // 27648
#define WB2_OFF (B1_OFF + STAGES * B_STG)    // 55296
#define WB2_SZ  (1024 * LDB * 2)             // 147456
#define BIAS_OFF (WB2_OFF + WB2_SZ)          // 202752
#define SMEM_BYTES (BIAS_OFF + 512 + 128)
#define Z1_OFF  (64 * LDZ * 4)               // zs1 at 18432 (z overlays A+B1 rings)

typedef __nv_bfloat16 bf16;

__device__ bf16  g_xT[TT * BB * FF];
__device__ bf16  g_img1[NTILES * 576 * NCOL];
__device__ bf16  g_img2[NTILES * 1024 * NCOL];
__device__ bf16  g_h1[2][BB * UU];
__device__ float g_c1[BB * UU];
__device__ bf16  g_h2[2][BB * UU];
__device__ float g_c2[BB * UU];
__device__ unsigned g_bar, g_gen;

__device__ __forceinline__ float sigmoidf_(float x) { return 1.f / (1.f + expf(-x)); }

#define CP_ASYNC16(dst, src) \
    asm volatile("cp.async.cg.shared.global [%0], [%1], 16;" :: "r"(dst), "l"(src))
#define CP_COMMIT() asm volatile("cp.async.commit_group;" ::: "memory")
#define CP_WAIT1()  asm volatile("cp.async.wait_group 1;" ::: "memory")
#define CP_WAIT0()  asm volatile("cp.async.wait_group 0;" ::: "memory")

// ---- consolidated prep ----
#define NB_ZERO 512
#define NB_X    16384
#define NB_I1   4608
#define NB_I2   8192

__device__ __forceinline__ void img_elem(const float* Wm, const float* Um,
                                         bf16* img, int KW, int Ktot, int e) {
    int n = e & 63;
    int k = (e >> 6) % Ktot;
    int tile = e / (Ktot * NCOL);
    int g = n >> 4, ui = n & 15;
    int col = g * UU + tile * 16 + ui;
    float v = (k < KW) ? Wm[k * GG + col] : Um[(k - KW) * GG + col];
    img[tile * (Ktot * NCOL) + (k >> 6) * (KC * NCOL) + (k & 63) * NCOL + n] =
        __float2bfloat16_rn(v);
}

__global__ void prep_all_kernel(const float* __restrict__ x,
                                const float* __restrict__ W1, const float* __restrict__ U1,
                                const float* __restrict__ W2, const float* __restrict__ U2) {
    int bx = blockIdx.x;
    if (bx < NB_ZERO) {
        int i = bx * 256 + threadIdx.x;
        g_h1[0][i] = __float2bfloat16_rn(0.f);
        g_h2[0][i] = __float2bfloat16_rn(0.f);
        g_c1[i] = 0.f;
        g_c2[i] = 0.f;
        if (i == 0) { g_bar = 0u; g_gen = 0u; }
    } else if (bx < NB_ZERO + NB_X) {
        int e = (bx - NB_ZERO) * 256 + threadIdx.x;
        int f = e & 63, t = (e >> 6) & 255, b = e >> 14;
        g_xT[t * (BB * FF) + b * FF + f] = __float2bfloat16_rn(x[e]);
    } else if (bx < NB_ZERO + NB_X + NB_I1) {
        int e = (bx - NB_ZERO - NB_X) * 256 + threadIdx.x;
        img_elem(W1, U1, g_img1, FF, 576, e);
    } else {
        int e = (bx - NB_ZERO - NB_X - NB_I1) * 256 + threadIdx.x;
        img_elem(W2, U2, g_img2, UU, 1024, e);
    }
}

// release/acquire grid barrier across 128 resident CTAs
__device__ __forceinline__ void grid_barrier(unsigned phase) {
    __threadfence();
    __syncthreads();
    if (threadIdx.x == 0) {
        unsigned old = atomicAdd(&g_bar, 1u);
        if (old == phase * NCTA - 1u) {
            atomicExch(&g_gen, phase);
        } else {
            while (*(volatile unsigned*)&g_gen < phase) __nanosleep(64);
        }
    }
    __syncthreads();
    __threadfence();
}

// Skewed persistent kernel: phase p runs layer1(step p) and layer2(step p-1)
// back-to-back in ONE merged 25-chunk pipeline, one grid barrier per phase.
__global__ void __launch_bounds__(NTHR, 1)
lstm_persistent(const float* __restrict__ b1, const float* __restrict__ b2)
{
    extern __shared__ __align__(1024) char smem[];
    uint32_t sb = (uint32_t)__cvta_generic_to_shared(smem);

    const int tid = threadIdx.x, wid = tid >> 5;
    const int bx = blockIdx.x;
    const int bM = (bx & 3) * 64;
    const int tile = bx >> 2;
    const int u0 = tile * 16;
    const int w_m = wid & 1, w_n = (wid >> 1) & 1, w_k = wid >> 2;

    float* bsm1 = (float*)(smem + BIAS_OFF);
    float* bsm2 = bsm1 + 64;
    if (tid < 64) {
        int g = tid >> 4, ui = tid & 15;
        bsm1[tid] = b1[g * UU + tile * 16 + ui];
        bsm2[tid] = b2[g * UU + tile * 16 + ui];
    }

    const bf16* img1b = g_img1 + (size_t)tile * (576 * NCOL);
    const bf16* img2b = g_img2 + (size_t)tile * (1024 * NCOL);

    // prologue: resident W2 tile (1024 x 64 -> [k][LDB])
    {
        const char* src = (const char*)img2b;
        uint32_t dst = sb + WB2_OFF;
#pragma unroll 1
        for (int u = tid; u < 1024 * 8; u += NTHR) {
            int row = u >> 3, nq = u & 7;
            CP_ASYNC16(dst + (uint32_t)(row * (LDB * 2) + nq * 16), src + u * 16);
        }
        CP_COMMIT();
        CP_WAIT0();
    }
    __syncthreads();

    bf16* As = (bf16*)smem;

    // chunk c of phase p: c<C1N -> layer1 (A + streamed B1); else layer2 (A only)
    auto load_chunk = [&](int c, int p) {
        int slot = c % STAGES;
        const bf16* as; int lda, k0;
        if (c == 0)          { as = g_xT + (size_t)p * BB * FF; lda = FF; k0 = 0; }
        else if (c < C1N)    { as = g_h1[p & 1]; lda = UU; k0 = (c - 1) * KC; }
        else if (c < C1N + 8){ as = g_h1[p & 1]; lda = UU; k0 = (c - C1N) * KC; }
        else                 { as = g_h2[(p - 1) & 1]; lda = UU; k0 = (c - C1N - 8) * KC; }
        uint32_t adst = sb + A_OFF + slot * A_STG;
#pragma unroll
        for (int j = 0; j < 2; j++) {
            int u = tid + NTHR * j, m = u >> 3, kq = u & 7;
            CP_ASYNC16(adst + (uint32_t)(m * (LDA * 2) + kq * 16),
                       as + (size_t)(bM + m) * lda + k0 + kq * 8);
        }
        if (c < C1N) {
            const char* wsrc = (const char*)img1b + (size_t)c * (KC * NCOL * 2);
            uint32_t bdst = sb + B1_OFF + slot * B_STG;
#pragma unroll
            for (int j = 0; j < 2; j++) {
                int u = tid + NTHR * j, k = u >> 3, nq = u & 7;
                CP_ASYNC16(bdst + (uint32_t)(k * (LDB * 2) + nq * 16), wsrc + u * 16);
            }
        }
        CP_COMMIT();
    };

    auto epilogue = [&](const float* bsm, float* cstate, bf16* hout) {
        float* zs0 = (float*)smem;
        float* zs1 = (float*)(smem + Z1_OFF);
        const int u  = tid & 15;
        const int bq = tid >> 4;
        const float bi = bsm[u], bf_ = bsm[16 + u], bg = bsm[32 + u], bo = bsm[48 + u];
#pragma unroll
        for (int j = 0; j < 4; j++) {
            const int m = bq * 4 + j;
            const size_t idx = (size_t)(bM + m) * UU + u0 + u;
            const float zi = zs0[m * LDZ + u]      + zs1[m * LDZ + u]      + bi;
            const float zf = zs0[m * LDZ + 16 + u] + zs1[m * LDZ + 16 + u] + bf_;
            const float zg = zs0[m * LDZ + 32 + u] + zs1[m * LDZ + 32 + u] + bg;
            const float zo = zs0[m * LDZ + 48 + u] + zs1[m * LDZ + 48 + u] + bo;
            const float ig = sigmoidf_(zi);
            const float fg = sigmoidf_(zf);
            const float gg = fmaxf(zg, 0.f);
            const float og = sigmoidf_(zo);
            const float c  = fg * cstate[idx] + ig * gg;
            cstate[idx] = c;
            hout[idx]   = __float2bfloat16_rn(og * fmaxf(c, 0.f));
        }
    };

#pragma unroll 1
    for (int p = 0; p <= TT; p++) {
        const bool do1 = (p < TT), do2 = (p > 0);
        const int c0 = do1 ? 0 : C1N;
        const int c1 = do2 ? CTOT : C1N;

        wmma::fragment<wmma::accumulator, 16, 16, 16, float> acc1[2][2], acc2[2][2];
#pragma unroll
        for (int q = 0; q < 2; q++)
#pragma unroll
            for (int r = 0; r < 2; r++) {
                wmma::fill_fragment(acc1[q][r], 0.f);
                wmma::fill_fragment(acc2[q][r], 0.f);
            }

        load_chunk(c0, p);
        load_chunk(c0 + 1, p);

#pragma unroll 1
        for (int c = c0; c < c1; c++) {
            CP_WAIT1();
            __syncthreads();
            int nc = c + 2;
            if (nc < c1) load_chunk(nc, p);
            else         CP_COMMIT();

            const bool l1 = (c < C1N);
            auto& acc = l1 ? acc1 : acc2;
            const bf16* Ab = As + (c % STAGES) * (64 * LDA) + (w_m * 32) * LDA;
            const bf16* Bb = l1
                ? (const bf16*)(smem + B1_OFF) + (c % STAGES) * (KC * LDB) + w_n * 32
                : (const bf16*)(smem + WB2_OFF) + (size_t)(c - C1N) * KC * LDB + w_n * 32;
            const int kof0 = (w_k * 2) * 16;

            wmma::fragment<wmma::matrix_a, 16, 16, 16, bf16, wmma::row_major> af[2][2];
            wmma::fragment<wmma::matrix_b, 16, 16, 16, bf16, wmma::row_major> bfr[2][2];
            wmma::load_matrix_sync(af[0][0], Ab + kof0, LDA);
            wmma::load_matrix_sync(af[0][1], Ab + 16 * LDA + kof0, LDA);
            wmma::load_matrix_sync(bfr[0][0], Bb + kof0 * LDB, LDB);
            wmma::load_matrix_sync(bfr[0][1], Bb + kof0 * LDB + 16, LDB);
#pragma unroll
            for (int s = 0; s < 2; s++) {
                if (s == 0) {
                    const int kof1 = kof0 + 16;
                    wmma::load_matrix_sync(af[1][0], Ab + kof1, LDA);
                    wmma::load_matrix_sync(af[1][1], Ab + 16 * LDA + kof1, LDA);
                    wmma::load_matrix_sync(bfr[1][0], Bb + kof1 * LDB, LDB);
                    wmma::load_matrix_sync(bfr[1][1], Bb + kof1 * LDB + 16, LDB);
                }
#pragma unroll
                for (int q = 0; q < 2; q++)
#pragma unroll
                    for (int r = 0; r < 2; r++)
                        wmma::mma_sync(acc[q][r], af[s][q], bfr[s][r], acc[q][r]);
            }
        }

        CP_WAIT0();
        __syncthreads();
        float* zs0 = (float*)smem;
        float* zs1 = (float*)(smem + Z1_OFF);
        float* zsw = w_k ? zs1 : zs0;

        if (do1) {
#pragma unroll
            for (int q = 0; q < 2; q++)
#pragma unroll
                for (int r = 0; r < 2; r++)
                    wmma::store_matrix_sync(zsw + (w_m * 32 + 16 * q) * LDZ + (w_n * 32 + 16 * r),
                                            acc1[q][r], LDZ, wmma::mem_row_major);
            __syncthreads();
            epilogue(bsm1, g_c1, g_h1[(p + 1) & 1]);
            __syncthreads();
        }
        if (do2) {
#pragma unroll
            for (int q = 0; q < 2; q++)
#pragma unroll
                for (int r = 0; r < 2; r++)
                    wmma::store_matrix_sync(zsw + (w_m * 32 + 16 * q) * LDZ + (w_n * 32 + 16 * r),
                                            acc2[q][r], LDZ, wmma::mem_row_major);
            __syncthreads();
            epilogue(bsm2, g_c2, g_h2[p & 1]);
        }

        grid_barrier((unsigned)(p + 1));
    }
}

__global__ void head_kernel(const float* __restrict__ Wd,
                            const float* __restrict__ bd,
                            float* __restrict__ out)
{
    const int b = threadIdx.x;
    float s = 0.f;
#pragma unroll 8
    for (int k = 0; k < UU; k++) s = fmaf(__bfloat162float(g_h2[0][b * UU + k]), Wd[k], s);
    out[b] = 1.f / (1.f + expf(-(s + bd[0])));
}

extern "C" void kernel_launch(void* const* d_in, const int* in_sizes, int n_in,
                              void* d_out, int out_size) {
    const float* x  = (const float*)d_in[0];
    const float* W1 = (const float*)d_in[1];
    const float* U1 = (const float*)d_in[2];
    const float* b1 = (const float*)d_in[3];
    const float* W2 = (const float*)d_in[4];
    const float* U2 = (const float*)d_in[5];
    const float* b2 = (const float*)d_in[6];
    const float* Wd = (const float*)d_in[7];
    const float* bd = (const float*)d_in[8];
    float* out = (float*)d_out;

    cudaFuncSetAttribute(lstm_persistent, cudaFuncAttributeMaxDynamicSharedMemorySize, SMEM_BYTES);

    prep_all_kernel<<<NB_ZERO + NB_X + NB_I1 + NB_I2, 256>>>(x, W1, U1, W2, U2);

    lstm_persistent<<<NCTA, NTHR, SMEM_BYTES>>>(b1, b2);

    head_kernel<<<1, 256>>>(Wd, bd, out);
}